// round 2
// baseline (speedup 1.0000x reference)
#include <cuda_runtime.h>
#include <math.h>

#define NUM_JOINTS 50
#define FEAT 150
#define NUM_BONES 50
#define FRAMES_PER_CHUNK 32
#define ROW 151                      // padded row (odd -> conflict-free LDS)
#define THREADS 128
#define CHUNK_ELEMS (FRAMES_PER_CHUNK * FEAT)   // 4800
#define CHUNK_VEC4  (CHUNK_ELEMS / 4)           // 1200
#define TINY 1.17549435e-38f

__constant__ int c_ba[NUM_BONES] = {
    0,1,2,3,1,5,6,
    7,8,9,10,11,8,13,14,15,8,17,18,19,8,21,22,23,8,25,26,27,
    4,29,30,31,32,29,34,35,36,29,38,39,40,29,42,43,44,29,46,47,48,
    0
};
__constant__ int c_bb[NUM_BONES] = {
    1,2,3,4,5,6,7,
    8,9,10,11,12,13,14,15,16,17,18,19,20,21,22,23,24,25,26,27,28,
    29,30,31,32,33,34,35,36,37,38,39,40,41,42,43,44,45,46,47,48,49,
    2
};

__device__ double g_acc[2];

__global__ void zero_acc_kernel() {
    g_acc[0] = 0.0;
    g_acc[1] = 0.0;
}

__global__ void __launch_bounds__(THREADS)
loss_main_kernel(const float* __restrict__ preds,
                 const float* __restrict__ tgts,
                 int n_chunks)
{
    __shared__ float Psh[FRAMES_PER_CHUNK][ROW];
    __shared__ float Tsh[FRAMES_PER_CHUNK][ROW];
    __shared__ float wL[THREADS / 32];
    __shared__ float wS[THREADS / 32];

    const int tid = threadIdx.x;
    const int fid = tid >> 2;    // 0..31 frame within chunk
    const int sub = tid & 3;     // 0..3 sub-worker within frame

    float sL1 = 0.0f;
    float sSq = 0.0f;

    for (int ch = blockIdx.x; ch < n_chunks; ch += gridDim.x) {
        const float4* __restrict__ p4 =
            (const float4*)(preds + (size_t)ch * CHUNK_ELEMS);
        const float4* __restrict__ t4 =
            (const float4*)(tgts  + (size_t)ch * CHUNK_ELEMS);

        __syncthreads();   // previous compute done before overwrite
        #pragma unroll 2
        for (int i = tid; i < CHUNK_VEC4; i += THREADS) {
            float4 v = p4[i];
            float4 w = t4[i];
            int e0 = i * 4;
            #pragma unroll
            for (int j = 0; j < 4; ++j) {
                int e = e0 + j;
                int f = e / FEAT;
                int p = e - f * FEAT;
                float pv = (j == 0) ? v.x : (j == 1) ? v.y : (j == 2) ? v.z : v.w;
                float tv = (j == 0) ? w.x : (j == 1) ? w.y : (j == 2) ? w.z : w.w;
                Psh[f][p] = pv;
                Tsh[f][p] = tv;
            }
        }
        __syncthreads();

        const float* __restrict__ P = Psh[fid];
        const float* __restrict__ T = Tsh[fid];

        // L1 term: |pm - tm| = (t!=0) ? |p - t| : 0
        #pragma unroll 4
        for (int e = sub; e < FEAT; e += 4) {
            float t = T[e];
            if (t != 0.0f) sL1 += fabsf(P[e] - t);
        }

        // Bone direction MSE term
        for (int b = sub; b < NUM_BONES; b += 4) {
            int ja = c_ba[b] * 3;
            int jb = c_bb[b] * 3;

            float ta0 = T[ja], ta1 = T[ja + 1], ta2 = T[ja + 2];
            float tb0 = T[jb], tb1 = T[jb + 1], tb2 = T[jb + 2];
            float pa0 = (ta0 != 0.0f) ? P[ja]     : 0.0f;
            float pa1 = (ta1 != 0.0f) ? P[ja + 1] : 0.0f;
            float pa2 = (ta2 != 0.0f) ? P[ja + 2] : 0.0f;
            float pb0 = (tb0 != 0.0f) ? P[jb]     : 0.0f;
            float pb1 = (tb1 != 0.0f) ? P[jb + 1] : 0.0f;
            float pb2 = (tb2 != 0.0f) ? P[jb + 2] : 0.0f;

            float dp0 = pa0 - pb0, dp1 = pa1 - pb1, dp2 = pa2 - pb2;
            float dt0 = ta0 - tb0, dt1 = ta1 - tb1, dt2 = ta2 - tb2;

            float d2p = dp0 * dp0 + dp1 * dp1 + dp2 * dp2;
            float d2t = dt0 * dt0 + dt1 * dt1 + dt2 * dt2;

            float invp = 1.0f / (sqrtf(d2p) + TINY);
            float invt = 1.0f / (sqrtf(d2t) + TINY);

            int mb = b * 3;
            float m0 = (T[mb]     != 0.0f) ? 1.0f : 0.0f;
            float m1 = (T[mb + 1] != 0.0f) ? 1.0f : 0.0f;
            float m2 = (T[mb + 2] != 0.0f) ? 1.0f : 0.0f;

            float e0 = (dp0 * invp - dt0 * invt) * m0;
            float e1 = (dp1 * invp - dt1 * invt) * m1;
            float e2 = (dp2 * invp - dt2 * invt) * m2;
            sSq += e0 * e0 + e1 * e1 + e2 * e2;
        }
    }

    // warp reduce
    #pragma unroll
    for (int off = 16; off; off >>= 1) {
        sL1 += __shfl_down_sync(0xFFFFFFFFu, sL1, off);
        sSq += __shfl_down_sync(0xFFFFFFFFu, sSq, off);
    }
    if ((tid & 31) == 0) {
        wL[tid >> 5] = sL1;
        wS[tid >> 5] = sSq;
    }
    __syncthreads();
    if (tid == 0) {
        float bL = wL[0] + wL[1] + wL[2] + wL[3];
        float bS = wS[0] + wS[1] + wS[2] + wS[3];
        atomicAdd(&g_acc[0], (double)bL);
        atomicAdd(&g_acc[1], (double)bS);
    }
}

__global__ void finalize_kernel(float* out, double inv_n) {
    out[0] = (float)(g_acc[0] * inv_n + 0.1 * g_acc[1] * inv_n);
}

extern "C" void kernel_launch(void* const* d_in, const int* in_sizes, int n_in,
                              void* d_out, int out_size)
{
    const float* preds = (const float*)d_in[0];
    const float* tgts  = (const float*)d_in[1];
    float* out = (float*)d_out;

    const long long total = (long long)in_sizes[0];           // 39,321,600
    const int n_chunks = (int)(total / CHUNK_ELEMS);          // 8192
    const double inv_n = 1.0 / (double)total;

    zero_acc_kernel<<<1, 1>>>();
    int grid = 148 * 5;
    if (grid > n_chunks) grid = n_chunks;
    loss_main_kernel<<<grid, THREADS>>>(preds, tgts, n_chunks);
    finalize_kernel<<<1, 1>>>(out, inv_n);
}

// round 3
// speedup vs baseline: 1.3026x; 1.3026x over previous
#include <cuda_runtime.h>
#include <math.h>

#define NUM_JOINTS 50
#define FEAT 150
#define NUM_BONES 50
#define FRAMES_PER_CHUNK 32
#define THREADS 128
#define CHUNK_ELEMS (FRAMES_PER_CHUNK * FEAT)   // 4800
#define CHUNK_VEC4  (CHUNK_ELEMS / 4)           // 1200

__constant__ int c_ba[NUM_BONES] = {
    0,1,2,3,1,5,6,
    7,8,9,10,11,8,13,14,15,8,17,18,19,8,21,22,23,8,25,26,27,
    4,29,30,31,32,29,34,35,36,29,38,39,40,29,42,43,44,29,46,47,48,
    0
};
__constant__ int c_bb[NUM_BONES] = {
    1,2,3,4,5,6,7,
    8,9,10,11,12,13,14,15,16,17,18,19,20,21,22,23,24,25,26,27,28,
    29,30,31,32,33,34,35,36,37,38,39,40,41,42,43,44,45,46,47,48,49,
    2
};

__device__ double g_acc[2];

__global__ void zero_acc_kernel() {
    g_acc[0] = 0.0;
    g_acc[1] = 0.0;
}

__global__ void __launch_bounds__(THREADS)
loss_main_kernel(const float* __restrict__ preds,
                 const float* __restrict__ tgts,
                 int n_chunks)
{
    __shared__ float Psh[CHUNK_ELEMS];   // linear, frame f at offset f*150
    __shared__ float Tsh[CHUNK_ELEMS];
    __shared__ float wL[THREADS / 32];
    __shared__ float wS[THREADS / 32];

    const int tid = threadIdx.x;
    const int fid = tid >> 2;    // 0..31 frame within chunk
    const int sub = tid & 3;     // 0..3 sub-worker within frame

    float sL1 = 0.0f;
    float sSq = 0.0f;

    float4* Ps4 = (float4*)Psh;
    float4* Ts4 = (float4*)Tsh;

    for (int ch = blockIdx.x; ch < n_chunks; ch += gridDim.x) {
        const float4* __restrict__ p4 =
            (const float4*)(preds + (size_t)ch * CHUNK_ELEMS);
        const float4* __restrict__ t4 =
            (const float4*)(tgts  + (size_t)ch * CHUNK_ELEMS);

        __syncthreads();   // previous compute done before overwrite
        #pragma unroll
        for (int k = 0; k < CHUNK_VEC4 / THREADS; ++k) {     // 9 full passes
            int i = k * THREADS + tid;
            Ps4[i] = p4[i];
            Ts4[i] = t4[i];
        }
        {
            int i = (CHUNK_VEC4 / THREADS) * THREADS + tid;  // tail: 48 vec4
            if (i < CHUNK_VEC4) {
                Ps4[i] = p4[i];
                Ts4[i] = t4[i];
            }
        }
        __syncthreads();

        const float* __restrict__ P = Psh + fid * FEAT;
        const float* __restrict__ T = Tsh + fid * FEAT;

        // L1 term: |pm - tm| = (t!=0) ? |p - t| : 0
        #pragma unroll 8
        for (int e = sub; e < FEAT; e += 4) {
            float t = T[e];
            float d = fabsf(P[e] - t);
            sL1 += (t != 0.0f) ? d : 0.0f;
        }

        // Bone direction MSE term
        for (int b = sub; b < NUM_BONES; b += 4) {
            int ja = c_ba[b] * 3;
            int jb = c_bb[b] * 3;

            float ta0 = T[ja], ta1 = T[ja + 1], ta2 = T[ja + 2];
            float tb0 = T[jb], tb1 = T[jb + 1], tb2 = T[jb + 2];
            float pa0 = (ta0 != 0.0f) ? P[ja]     : 0.0f;
            float pa1 = (ta1 != 0.0f) ? P[ja + 1] : 0.0f;
            float pa2 = (ta2 != 0.0f) ? P[ja + 2] : 0.0f;
            float pb0 = (tb0 != 0.0f) ? P[jb]     : 0.0f;
            float pb1 = (tb1 != 0.0f) ? P[jb + 1] : 0.0f;
            float pb2 = (tb2 != 0.0f) ? P[jb + 2] : 0.0f;

            float dp0 = pa0 - pb0, dp1 = pa1 - pb1, dp2 = pa2 - pb2;
            float dt0 = ta0 - tb0, dt1 = ta1 - tb1, dt2 = ta2 - tb2;

            float d2p = dp0 * dp0 + dp1 * dp1 + dp2 * dp2;
            float d2t = dt0 * dt0 + dt1 * dt1 + dt2 * dt2;

            // 1/(sqrt(d2)+tiny): d2>0 -> rsqrt; d2==0 -> diff is 0, so any
            // finite inv gives the same 0 contribution; use 0.
            float invp = (d2p > 0.0f) ? rsqrtf(d2p) : 0.0f;
            float invt = (d2t > 0.0f) ? rsqrtf(d2t) : 0.0f;

            int mb = b * 3;
            float m0 = (T[mb]     != 0.0f) ? 1.0f : 0.0f;
            float m1 = (T[mb + 1] != 0.0f) ? 1.0f : 0.0f;
            float m2 = (T[mb + 2] != 0.0f) ? 1.0f : 0.0f;

            float e0 = (dp0 * invp - dt0 * invt) * m0;
            float e1 = (dp1 * invp - dt1 * invt) * m1;
            float e2 = (dp2 * invp - dt2 * invt) * m2;
            sSq += e0 * e0 + e1 * e1 + e2 * e2;
        }
    }

    // warp reduce
    #pragma unroll
    for (int off = 16; off; off >>= 1) {
        sL1 += __shfl_down_sync(0xFFFFFFFFu, sL1, off);
        sSq += __shfl_down_sync(0xFFFFFFFFu, sSq, off);
    }
    if ((tid & 31) == 0) {
        wL[tid >> 5] = sL1;
        wS[tid >> 5] = sSq;
    }
    __syncthreads();
    if (tid == 0) {
        float bL = wL[0] + wL[1] + wL[2] + wL[3];
        float bS = wS[0] + wS[1] + wS[2] + wS[3];
        atomicAdd(&g_acc[0], (double)bL);
        atomicAdd(&g_acc[1], (double)bS);
    }
}

__global__ void finalize_kernel(float* out, double inv_n) {
    out[0] = (float)((g_acc[0] + 0.1 * g_acc[1]) * inv_n);
}

extern "C" void kernel_launch(void* const* d_in, const int* in_sizes, int n_in,
                              void* d_out, int out_size)
{
    const float* preds = (const float*)d_in[0];
    const float* tgts  = (const float*)d_in[1];
    float* out = (float*)d_out;

    const long long total = (long long)in_sizes[0];           // 39,321,600
    const int n_chunks = (int)(total / CHUNK_ELEMS);          // 8192
    const double inv_n = 1.0 / (double)total;

    zero_acc_kernel<<<1, 1>>>();
    int grid = 148 * 5;
    if (grid > n_chunks) grid = n_chunks;
    loss_main_kernel<<<grid, THREADS>>>(preds, tgts, n_chunks);
    finalize_kernel<<<1, 1>>>(out, inv_n);
}